// round 5
// baseline (speedup 1.0000x reference)
#include <cuda_runtime.h>
#include <cuda_bf16.h>
#include <math.h>
#include <stdint.h>

#define B_    2
#define T_    2048
#define D_    1024
#define H_    16
#define HD_   64
#define WIN_  512
#define ROWS_ (B_*T_)   // 4096

// ---------------- scratch (device globals; no runtime alloc) ----------------
__device__ float g_qkv[ROWS_ * 3 * D_];
__device__ __nv_bfloat16 g_xhi [ROWS_*D_];
__device__ __nv_bfloat16 g_xlo [ROWS_*D_];
__device__ __nv_bfloat16 g_qhi [ROWS_*D_];
__device__ __nv_bfloat16 g_qlo [ROWS_*D_];
__device__ __nv_bfloat16 g_khi [ROWS_*D_];
__device__ __nv_bfloat16 g_klo [ROWS_*D_];
__device__ __nv_bfloat16 g_vhi [ROWS_*D_];
__device__ __nv_bfloat16 g_vlo [ROWS_*D_];
__device__ __nv_bfloat16 g_aohi[ROWS_*D_];
__device__ __nv_bfloat16 g_aolo[ROWS_*D_];
__device__ __nv_bfloat16 g_whi [4 * D_ * D_];    // wq|wk|wv|wo
__device__ __nv_bfloat16 g_wlo [4 * D_ * D_];

__device__ __forceinline__ uint32_t smem_to_u32(const void* p) {
    uint32_t a;
    asm("{ .reg .u64 t; cvta.to.shared.u64 t, %1; cvt.u32.u64 %0, t; }"
        : "=r"(a) : "l"(p));
    return a;
}

#define LDSM4(r, addr) \
    asm volatile("ldmatrix.sync.aligned.m8n8.x4.shared.b16 {%0,%1,%2,%3}, [%4];" \
        : "=r"((r)[0]), "=r"((r)[1]), "=r"((r)[2]), "=r"((r)[3]) : "r"(addr))
#define LDSM4T(r, addr) \
    asm volatile("ldmatrix.sync.aligned.m8n8.x4.trans.shared.b16 {%0,%1,%2,%3}, [%4];" \
        : "=r"((r)[0]), "=r"((r)[1]), "=r"((r)[2]), "=r"((r)[3]) : "r"(addr))

#define MMA_BF16(c, a, b0, b1) \
    asm volatile("mma.sync.aligned.m16n8k16.row.col.f32.bf16.bf16.f32 " \
        "{%0,%1,%2,%3}, {%4,%5,%6,%7}, {%8,%9}, {%0,%1,%2,%3};" \
        : "+f"((c)[0]), "+f"((c)[1]), "+f"((c)[2]), "+f"((c)[3]) \
        : "r"((a)[0]), "r"((a)[1]), "r"((a)[2]), "r"((a)[3]), "r"(b0), "r"(b1))

#define CP_ASYNC16(sa, gp) \
    asm volatile("cp.async.cg.shared.global [%0], [%1], 16;\n" :: "r"(sa), "l"(gp))
#define CP_COMMIT()  asm volatile("cp.async.commit_group;\n" ::: "memory")
#define CP_WAIT(n)   asm volatile("cp.async.wait_group %0;\n" :: "n"(n) : "memory")

__device__ __forceinline__ uint32_t pack_bf16x2(float lo, float hi) {
    union { __nv_bfloat162 h; uint32_t u; } t;
    t.h = __float22bfloat162_rn(make_float2(lo, hi));
    return t.u;
}

// ---------------------------------------------------------------------------
// fp32 -> bf16 hi/lo split kernels
// ---------------------------------------------------------------------------
__global__ __launch_bounds__(256) void cvt_split(const float* __restrict__ in,
                                                 __nv_bfloat16* __restrict__ hi,
                                                 __nv_bfloat16* __restrict__ lo,
                                                 int n8)
{
    int u = blockIdx.x * 256 + threadIdx.x;
    if (u >= n8) return;
    const float4* p = (const float4*)in + (size_t)u * 2;
    float4 a = p[0], b = p[1];
    float f[8] = {a.x, a.y, a.z, a.w, b.x, b.y, b.z, b.w};
    union { __nv_bfloat16 h[8]; uint4 u4; } ph, pl;
#pragma unroll
    for (int j = 0; j < 8; j++) {
        __nv_bfloat16 h = __float2bfloat16_rn(f[j]);
        ph.h[j] = h;
        pl.h[j] = __float2bfloat16_rn(f[j] - __bfloat162float(h));
    }
    *(uint4*)(hi + (size_t)u * 8) = ph.u4;
    *(uint4*)(lo + (size_t)u * 8) = pl.u4;
}

__global__ __launch_bounds__(256) void cvt_w(const float* __restrict__ w0,
                                             const float* __restrict__ w1,
                                             const float* __restrict__ w2,
                                             const float* __restrict__ w3)
{
    const int wsel = blockIdx.y;
    const float* src = (wsel == 0) ? w0 : (wsel == 1) ? w1 : (wsel == 2) ? w2 : w3;
    __nv_bfloat16* hi = g_whi + (size_t)wsel * D_ * D_;
    __nv_bfloat16* lo = g_wlo + (size_t)wsel * D_ * D_;
    int u = blockIdx.x * 256 + threadIdx.x;
    const float4* p = (const float4*)src + (size_t)u * 2;
    float4 a = p[0], b = p[1];
    float f[8] = {a.x, a.y, a.z, a.w, b.x, b.y, b.z, b.w};
    union { __nv_bfloat16 h[8]; uint4 u4; } ph, pl;
#pragma unroll
    for (int j = 0; j < 8; j++) {
        __nv_bfloat16 h = __float2bfloat16_rn(f[j]);
        ph.h[j] = h;
        pl.h[j] = __float2bfloat16_rn(f[j] - __bfloat162float(h));
    }
    *(uint4*)(hi + (size_t)u * 8) = ph.u4;
    *(uint4*)(lo + (size_t)u * 8) = pl.u4;
}

// ---------------------------------------------------------------------------
// HMMA bf16 split GEMM v2: 256x128 CTA tile, 512 threads (16 warps x 64x32),
// K-chunk 32, 3-stage cp.async pipeline.
// Stage layout: Ahi[256x80] Alo[256x80] Whi[128x80] Wlo[128x80] = 61440 B.
// ---------------------------------------------------------------------------
#define GA_TILE  20480           // 256*80
#define GW_TILE  10240           // 128*80
#define GSTAGE   61440
#define GEMM_SMEM (3 * GSTAGE)   // 184320

__global__ __launch_bounds__(512) void gemm_hmma(
    const __nv_bfloat16* __restrict__ Ahi, const __nv_bfloat16* __restrict__ Alo,
    const __nv_bfloat16* __restrict__ Whi, const __nv_bfloat16* __restrict__ Wlo,
    float* __restrict__ C, int M, int N, int K)
{
    extern __shared__ char smem[];
    const uint32_t sb = smem_to_u32(smem);
    const int tid  = threadIdx.x;
    const int lane = tid & 31;
    const int wid  = tid >> 5;
    const int wm   = (wid & 3) * 64;     // 0..192
    const int wn   = (wid >> 2) * 32;    // 0..96
    const int m0   = blockIdx.y * 256;
    const int n0   = blockIdx.x * 128;
    const int NCH  = K >> 5;

    auto issue = [&](int ch, int stg) {
        const int k0 = ch << 5;
        const uint32_t base = sb + (uint32_t)stg * GSTAGE;
        {
            const int row = tid >> 1;             // 0..255
            const int q   = (tid & 1) * 2;        // 2x16B per thread per half
            const size_t ga = (size_t)(m0 + row) * K + k0;
            const uint32_t sa = base + (uint32_t)(row * 80);
            CP_ASYNC16(sa + q * 16,            Ahi + ga + q * 8);
            CP_ASYNC16(sa + (q + 1) * 16,      Ahi + ga + (q + 1) * 8);
            CP_ASYNC16(sa + GA_TILE + q * 16,       Alo + ga + q * 8);
            CP_ASYNC16(sa + GA_TILE + (q + 1) * 16, Alo + ga + (q + 1) * 8);
        }
        {
            const int row = tid >> 2;             // 0..127
            const int q   = tid & 3;
            const size_t ga = (size_t)(n0 + row) * K + k0;
            const uint32_t sa = base + 2 * GA_TILE + (uint32_t)(row * 80 + q * 16);
            CP_ASYNC16(sa,           Whi + ga + q * 8);
            CP_ASYNC16(sa + GW_TILE, Wlo + ga + q * 8);
        }
        CP_COMMIT();
    };

    float acc[4][4][4];
#pragma unroll
    for (int mt = 0; mt < 4; mt++)
#pragma unroll
        for (int nt = 0; nt < 4; nt++)
#pragma unroll
            for (int e = 0; e < 4; e++) acc[mt][nt][e] = 0.f;

    issue(0, 0);
    issue(1, 1);

    for (int i = 0; i < NCH; i++) {
        const int stg = i % 3;
        if (i + 2 < NCH)       { issue(i + 2, (i + 2) % 3); CP_WAIT(2); }
        else if (i + 2 == NCH) { CP_WAIT(1); }
        else                   { CP_WAIT(0); }
        __syncthreads();

        const uint32_t base = sb + (uint32_t)stg * GSTAGE;
        const uint32_t aH = base, aL = base + GA_TILE;
        const uint32_t wH = base + 2 * GA_TILE, wL = wH + GW_TILE;

#pragma unroll
        for (int ks = 0; ks < 2; ks++) {
            const int kb = ks * 16;
            uint32_t ah[4][4], al[4][4], bh[2][4], bl[2][4];
            const uint32_t aOff = (uint32_t)((wm + (lane & 15)) * 80
                                             + (kb + (lane >> 4) * 8) * 2);
#pragma unroll
            for (int mt = 0; mt < 4; mt++) {
                LDSM4(ah[mt], aH + aOff + mt * 16 * 80);
                LDSM4(al[mt], aL + aOff + mt * 16 * 80);
            }
            const uint32_t bOff = (uint32_t)((wn + ((lane >> 4) * 8) + (lane & 7)) * 80
                                             + (kb + ((lane >> 3) & 1) * 8) * 2);
#pragma unroll
            for (int p = 0; p < 2; p++) {
                LDSM4(bh[p], wH + bOff + p * 16 * 80);
                LDSM4(bl[p], wL + bOff + p * 16 * 80);
            }
#pragma unroll
            for (int mt = 0; mt < 4; mt++)
#pragma unroll
                for (int nt = 0; nt < 4; nt++) {
                    const int p = nt >> 1, s = (nt & 1) * 2;
                    MMA_BF16(acc[mt][nt], ah[mt], bh[p][s], bh[p][s + 1]);
                    MMA_BF16(acc[mt][nt], ah[mt], bl[p][s], bl[p][s + 1]);
                    MMA_BF16(acc[mt][nt], al[mt], bh[p][s], bh[p][s + 1]);
                }
        }
        __syncthreads();
    }

#pragma unroll
    for (int mt = 0; mt < 4; mt++)
#pragma unroll
        for (int nt = 0; nt < 4; nt++) {
            const int r = m0 + wm + mt * 16 + (lane >> 2);
            const int c = n0 + wn + nt * 8 + (lane & 3) * 2;
            *(float2*)(C + (size_t)r * N + c) =
                make_float2(acc[mt][nt][0], acc[mt][nt][1]);
            *(float2*)(C + (size_t)(r + 8) * N + c) =
                make_float2(acc[mt][nt][2], acc[mt][nt][3]);
        }
}

// ---------------------------------------------------------------------------
// RMSNorm (q,k full-row) + bf16 hi/lo split of q,k,v from fused qkv buffer.
// ---------------------------------------------------------------------------
__global__ __launch_bounds__(256) void rms_split(const float* __restrict__ qw,
                                                 const float* __restrict__ kw)
{
    const int row = blockIdx.x;
    const int tid = threadIdx.x;
    const float* base = g_qkv + (size_t)row * 3 * D_;
    float4 qv = ((const float4*)(base        ))[tid];
    float4 kv = ((const float4*)(base +   D_))[tid];
    float4 vv = ((const float4*)(base + 2*D_))[tid];

    float sq = qv.x*qv.x + qv.y*qv.y + qv.z*qv.z + qv.w*qv.w;
    float sk = kv.x*kv.x + kv.y*kv.y + kv.z*kv.z + kv.w*kv.w;
#pragma unroll
    for (int o = 16; o > 0; o >>= 1) {
        sq += __shfl_xor_sync(0xffffffffu, sq, o);
        sk += __shfl_xor_sync(0xffffffffu, sk, o);
    }
    __shared__ float rq[8], rk[8];
    if ((tid & 31) == 0) { rq[tid >> 5] = sq; rk[tid >> 5] = sk; }
    __syncthreads();
    float tq = rq[0]+rq[1]+rq[2]+rq[3]+rq[4]+rq[5]+rq[6]+rq[7];
    float tk = rk[0]+rk[1]+rk[2]+rk[3]+rk[4]+rk[5]+rk[6]+rk[7];
    const float iq = rsqrtf(tq * (1.f / D_) + 1e-6f);
    const float ik = rsqrtf(tk * (1.f / D_) + 1e-6f);

    float4 qwv = ((const float4*)qw)[tid];
    float4 kwv = ((const float4*)kw)[tid];
    float qf[4] = {qv.x*iq*qwv.x, qv.y*iq*qwv.y, qv.z*iq*qwv.z, qv.w*iq*qwv.w};
    float kf[4] = {kv.x*ik*kwv.x, kv.y*ik*kwv.y, kv.z*ik*kwv.z, kv.w*ik*kwv.w};
    float vf[4] = {vv.x, vv.y, vv.z, vv.w};

    union { __nv_bfloat16 h[4]; uint2 u2; } o1, o2;
    const size_t idx = (size_t)row * D_ + tid * 4;
#pragma unroll
    for (int j = 0; j < 4; j++) {
        __nv_bfloat16 h = __float2bfloat16_rn(qf[j]);
        o1.h[j] = h; o2.h[j] = __float2bfloat16_rn(qf[j] - __bfloat162float(h));
    }
    *(uint2*)(g_qhi + idx) = o1.u2; *(uint2*)(g_qlo + idx) = o2.u2;
#pragma unroll
    for (int j = 0; j < 4; j++) {
        __nv_bfloat16 h = __float2bfloat16_rn(kf[j]);
        o1.h[j] = h; o2.h[j] = __float2bfloat16_rn(kf[j] - __bfloat162float(h));
    }
    *(uint2*)(g_khi + idx) = o1.u2; *(uint2*)(g_klo + idx) = o2.u2;
#pragma unroll
    for (int j = 0; j < 4; j++) {
        __nv_bfloat16 h = __float2bfloat16_rn(vf[j]);
        o1.h[j] = h; o2.h[j] = __float2bfloat16_rn(vf[j] - __bfloat162float(h));
    }
    *(uint2*)(g_vhi + idx) = o1.u2; *(uint2*)(g_vlo + idx) = o2.u2;
}

// ---------------------------------------------------------------------------
// HMMA flash attention v2: 128-row Q tiles, 8 warps, double-buffered K/V.
// smem rows 144 B. Q: 128 rows; K/V: 64 rows x 2 stages.
// ---------------------------------------------------------------------------
#define AT_RB   144
#define AQ_TILE (128 * AT_RB)    // 18432
#define AK_TILE (64 * AT_RB)     // 9216
#define SM_QH   0
#define SM_QL   AQ_TILE
#define SM_KV0  (2 * AQ_TILE)            // stage base: KH, KL, VH, VL
#define AKV_STG (4 * AK_TILE)            // 36864
#define ATTN_SMEM (2 * AQ_TILE + 2 * AKV_STG)  // 110592

__global__ __launch_bounds__(256) void attn_mma()
{
    extern __shared__ char smem[];
    const uint32_t sb = smem_to_u32(smem);
    const int tid  = threadIdx.x;
    const int lane = tid & 31;
    const int wid  = tid >> 5;
    const int b    = blockIdx.y >> 4;
    const int h    = blockIdx.y & 15;
    const int m0   = blockIdx.x * 128;
    const float slope = exp2f(-0.5f * (float)(h + 1));
    const float scale = 0.125f;
    const size_t rowbase = (size_t)b * T_;
    const int    hc      = h * HD_;

    const int jb0 = max(0, m0 - WIN_) >> 6;
    const int jb1 = (m0 >> 6) + 1;

    auto issueKV = [&](int jb, int stg) {
        const int n0 = jb << 6;
        const uint32_t base = sb + SM_KV0 + (uint32_t)stg * AKV_STG;
        for (int u = tid; u < 512; u += 256) {
            const int r = u >> 3, c = u & 7;
            const size_t g = (rowbase + n0 + r) * D_ + hc + c * 8;
            const uint32_t so = (uint32_t)(r * AT_RB + c * 16);
            CP_ASYNC16(base + 0 * AK_TILE + so, g_khi + g);
            CP_ASYNC16(base + 1 * AK_TILE + so, g_klo + g);
            CP_ASYNC16(base + 2 * AK_TILE + so, g_vhi + g);
            CP_ASYNC16(base + 3 * AK_TILE + so, g_vlo + g);
        }
    };

    // Q tile (128 rows) + first K/V block in group 0
    for (int u = tid; u < 1024; u += 256) {
        const int r = u >> 3, c = u & 7;
        const size_t g = (rowbase + m0 + r) * D_ + hc + c * 8;
        const uint32_t so = (uint32_t)(r * AT_RB + c * 16);
        CP_ASYNC16(sb + SM_QH + so, g_qhi + g);
        CP_ASYNC16(sb + SM_QL + so, g_qlo + g);
    }
    issueKV(jb0, 0);
    CP_COMMIT();

    float o[8][4];
    float mrow[2] = {-1e30f, -1e30f}, lrow[2] = {0.f, 0.f};
#pragma unroll
    for (int nf = 0; nf < 8; nf++)
#pragma unroll
        for (int e = 0; e < 4; e++) o[nf][e] = 0.f;

    const int r0a  = m0 + wid * 16 + (lane >> 2);
    const int col4 = (lane & 3) * 2;

    for (int jb = jb0; jb <= jb1; jb++) {
        const int n0  = jb << 6;
        const int stg = (jb - jb0) & 1;
        __syncthreads();   // all warps finished with stage stg^1
        if (jb < jb1) { issueKV(jb + 1, stg ^ 1); CP_COMMIT(); CP_WAIT(1); }
        else          { CP_WAIT(0); }
        __syncthreads();

        const uint32_t kvb = sb + SM_KV0 + (uint32_t)stg * AKV_STG;
        const uint32_t kH = kvb, kL = kvb + AK_TILE;
        const uint32_t vH = kvb + 2 * AK_TILE, vL = kvb + 3 * AK_TILE;

        // ---- S = Q K^T ----
        float s[8][4];
#pragma unroll
        for (int nf = 0; nf < 8; nf++)
#pragma unroll
            for (int e = 0; e < 4; e++) s[nf][e] = 0.f;

#pragma unroll
        for (int kb = 0; kb < 4; kb++) {
            uint32_t qh4[4], ql4[4];
            const uint32_t aOff = (uint32_t)((wid * 16 + (lane & 15)) * AT_RB
                                             + (kb * 16 + (lane >> 4) * 8) * 2);
            LDSM4(qh4, sb + SM_QH + aOff);
            LDSM4(ql4, sb + SM_QL + aOff);
            const uint32_t bOff = (uint32_t)((((lane >> 4) * 8) + (lane & 7)) * AT_RB
                                             + (kb * 16 + ((lane >> 3) & 1) * 8) * 2);
#pragma unroll
            for (int g = 0; g < 4; g++) {
                uint32_t kh4[4], kl4[4];
                LDSM4(kh4, kH + bOff + g * 16 * AT_RB);
                LDSM4(kl4, kL + bOff + g * 16 * AT_RB);
                MMA_BF16(s[2*g],   qh4, kh4[0], kh4[1]);
                MMA_BF16(s[2*g],   qh4, kl4[0], kl4[1]);
                MMA_BF16(s[2*g],   ql4, kh4[0], kh4[1]);
                MMA_BF16(s[2*g+1], qh4, kh4[2], kh4[3]);
                MMA_BF16(s[2*g+1], qh4, kl4[2], kl4[3]);
                MMA_BF16(s[2*g+1], ql4, kh4[2], kh4[3]);
            }
        }

        // ---- online softmax ----
        float mx[2] = {-1e30f, -1e30f};
#pragma unroll
        for (int nf = 0; nf < 8; nf++) {
#pragma unroll
            for (int t = 0; t < 2; t++) {
                const int r = r0a + t * 8;
#pragma unroll
                for (int j = 0; j < 2; j++) {
                    const int c = n0 + nf * 8 + col4 + j;
                    float val = s[nf][2*t + j] * scale + slope * (float)(c - r);
                    const bool valid = (c <= r) && (c >= r - WIN_);
                    val = valid ? val : -1e30f;
                    s[nf][2*t + j] = val;
                    mx[t] = fmaxf(mx[t], val);
                }
            }
        }
#pragma unroll
        for (int t = 0; t < 2; t++) {
            mx[t] = fmaxf(mx[t], __shfl_xor_sync(0xffffffffu, mx[t], 1));
            mx[t] = fmaxf(mx[t], __shfl_xor_sync(0xffffffffu, mx[t], 2));
        }
        float nm[2], alpha[2], rs[2] = {0.f, 0.f};
#pragma unroll
        for (int t = 0; t < 2; t++) {
            nm[t]    = fmaxf(mrow[t], mx[t]);
            alpha[t] = __expf(mrow[t] - nm[t]);
        }
#pragma unroll
        for (int nf = 0; nf < 8; nf++)
#pragma unroll
            for (int t = 0; t < 2; t++)
#pragma unroll
                for (int j = 0; j < 2; j++) {
                    const float v = s[nf][2*t + j];
                    const float p = (v > -1e29f) ? __expf(v - nm[t]) : 0.f;
                    s[nf][2*t + j] = p;
                    rs[t] += p;
                }
#pragma unroll
        for (int t = 0; t < 2; t++) {
            rs[t] += __shfl_xor_sync(0xffffffffu, rs[t], 1);
            rs[t] += __shfl_xor_sync(0xffffffffu, rs[t], 2);
            lrow[t] = lrow[t] * alpha[t] + rs[t];
            mrow[t] = nm[t];
        }
#pragma unroll
        for (int nf = 0; nf < 8; nf++) {
            o[nf][0] *= alpha[0]; o[nf][1] *= alpha[0];
            o[nf][2] *= alpha[1]; o[nf][3] *= alpha[1];
        }

        // ---- pack P hi/lo ----
        uint32_t ph[4][4], pl[4][4];
#pragma unroll
        for (int kf = 0; kf < 4; kf++) {
            const int f0 = 2 * kf, f1 = 2 * kf + 1;
            const float e[8] = {s[f0][0], s[f0][1], s[f0][2], s[f0][3],
                                s[f1][0], s[f1][1], s[f1][2], s[f1][3]};
#pragma unroll
            for (int q = 0; q < 4; q++) {
                const float a0 = e[q*2], a1 = e[q*2+1];
                uint32_t hi = pack_bf16x2(a0, a1);
                union { uint32_t u; __nv_bfloat162 h; } t; t.u = hi;
                float2 hf = __bfloat1622float2(t.h);
                ph[kf][q] = hi;
                pl[kf][q] = pack_bf16x2(a0 - hf.x, a1 - hf.y);
            }
        }

        // ---- O += P V ----
#pragma unroll
        for (int kf = 0; kf < 4; kf++) {
            const uint32_t vRow = (uint32_t)((kf * 16 + ((lane >> 4) * 8) + (lane & 7)) * AT_RB);
            const uint32_t vCol = (uint32_t)((((lane >> 3) & 1) * 8) * 2);
#pragma unroll
            for (int g = 0; g < 4; g++) {
                uint32_t vh4[4], vl4[4];
                const uint32_t va = vRow + vCol + (uint32_t)(g * 32);
                LDSM4T(vh4, vH + va);
                LDSM4T(vl4, vL + va);
                MMA_BF16(o[2*g],   ph[kf], vh4[0], vh4[2]);
                MMA_BF16(o[2*g],   pl[kf], vh4[0], vh4[2]);
                MMA_BF16(o[2*g],   ph[kf], vl4[0], vl4[2]);
                MMA_BF16(o[2*g+1], ph[kf], vh4[1], vh4[3]);
                MMA_BF16(o[2*g+1], pl[kf], vh4[1], vh4[3]);
                MMA_BF16(o[2*g+1], ph[kf], vl4[1], vl4[3]);
            }
        }
    }

    // ---- epilogue ----
#pragma unroll
    for (int t = 0; t < 2; t++) {
        const int r = r0a + t * 8;
        const float inv = 1.f / lrow[t];
#pragma unroll
        for (int nf = 0; nf < 8; nf++) {
            const float x0 = o[nf][2*t]     * inv;
            const float x1 = o[nf][2*t + 1] * inv;
            const uint32_t hi = pack_bf16x2(x0, x1);
            union { uint32_t u; __nv_bfloat162 h; } w; w.u = hi;
            float2 hf = __bfloat1622float2(w.h);
            const uint32_t lo = pack_bf16x2(x0 - hf.x, x1 - hf.y);
            const size_t g = (rowbase + r) * D_ + hc + nf * 8 + col4;
            *(uint32_t*)(g_aohi + g) = hi;
            *(uint32_t*)(g_aolo + g) = lo;
        }
    }
}

// ---------------------------------------------------------------------------
extern "C" void kernel_launch(void* const* d_in, const int* in_sizes, int n_in,
                              void* d_out, int out_size)
{
    const float* x  = (const float*)d_in[0];
    const float* wq = (const float*)d_in[1];
    const float* wk = (const float*)d_in[2];
    const float* wv = (const float*)d_in[3];
    const float* wo = (const float*)d_in[4];
    const float* qw = (const float*)d_in[5];
    const float* kw = (const float*)d_in[6];
    float* out = (float*)d_out;

    float* qkv;
    cudaGetSymbolAddress((void**)&qkv, g_qkv);
    __nv_bfloat16 *xhi, *xlo, *aohi, *aolo, *whi, *wlo;
    cudaGetSymbolAddress((void**)&xhi,  g_xhi);
    cudaGetSymbolAddress((void**)&xlo,  g_xlo);
    cudaGetSymbolAddress((void**)&aohi, g_aohi);
    cudaGetSymbolAddress((void**)&aolo, g_aolo);
    cudaGetSymbolAddress((void**)&whi,  g_whi);
    cudaGetSymbolAddress((void**)&wlo,  g_wlo);

    cudaFuncSetAttribute(gemm_hmma, cudaFuncAttributeMaxDynamicSharedMemorySize,
                         GEMM_SMEM);
    cudaFuncSetAttribute(attn_mma, cudaFuncAttributeMaxDynamicSharedMemorySize,
                         ATTN_SMEM);

    const int nx8 = (ROWS_*D_) / 8;
    const int nw8 = (D_*D_) / 8;

    cvt_split<<<nx8 / 256, 256>>>(x, xhi, xlo, nx8);
    cvt_w<<<dim3(nw8 / 256, 4), 256>>>(wq, wk, wv, wo);

    // fused QKV projection: [4096,1024] @ [3072,1024]^T -> [4096,3072]
    gemm_hmma<<<dim3(3*D_/128, ROWS_/256), 512, GEMM_SMEM>>>(
        xhi, xlo, whi, wlo, qkv, ROWS_, 3*D_, D_);

    rms_split<<<ROWS_, 256>>>(qw, kw);

    attn_mma<<<dim3(T_/128, B_*H_), 256, ATTN_SMEM>>>();

    // output projection
    gemm_hmma<<<dim3(D_/128, ROWS_/256), 512, GEMM_SMEM>>>(
        aohi, aolo, whi + 3*(size_t)D_*D_, wlo + 3*(size_t)D_*D_,
        out, ROWS_, D_, D_);
}